// round 6
// baseline (speedup 1.0000x reference)
#include <cuda_runtime.h>
#include <cuda_bf16.h>
#include <cuda_fp16.h>
#include <math.h>
#include <cstdint>

#define NN   50000
#define EE   800000
#define ETOT (EE + NN)
#define FIN  256
#define HC   128      // HEADS*C1 = 8*16
#define NC   40
#define NSLOPE 0.2f
#define NB_SCAN ((NN + 1023) / 1024)   // 49

// ---------------- scratch -----------------------------------------------
__device__ int      g_deg[NN];
__device__ int      g_off[NN + 1];
__device__ int      g_cur[NN];
__device__ int      g_src[ETOT];
__device__ int      g_dst[ETOT];
__device__ int      g_csr[ETOT];
__device__ unsigned g_state[NB_SCAN];       // lookback: (sum<<2)|flag
__device__ uint4    g_h1h[NN * HC / 8];     // h1 in fp16 (gather buffer)
__device__ __half   g_w1t[HC * FIN];        // W1^T fp16: [n][k]
__device__ float    g_as1[NN * 8];
__device__ float    g_ad1[NN * 8];
__device__ float    g_out1[NN * HC];
__device__ float    g_h2 [NN * NC];
__device__ float    g_as2[NN];
__device__ float    g_ad2[NN];

// half2 <-> uint bit-cast
union H2U { unsigned u; __half2 h; };
__device__ __forceinline__ unsigned h2u(float a, float b) {
    H2U c; c.h = __floats2half2_rn(a, b); return c.u;
}
__device__ __forceinline__ float2 u_to_f2(unsigned u) {
    H2U c; c.u = u; return __half22float2(c.h);
}

// warp-level HMMA (PTX ISA sm_80+, valid on plain sm_103 target)
__device__ __forceinline__ void mma16816(float* d,
                                         unsigned a0, unsigned a1,
                                         unsigned a2, unsigned a3,
                                         unsigned b0, unsigned b1) {
    asm volatile(
        "mma.sync.aligned.m16n8k16.row.col.f32.f16.f16.f32 "
        "{%0,%1,%2,%3}, {%4,%5,%6,%7}, {%8,%9}, {%0,%1,%2,%3};"
        : "+f"(d[0]), "+f"(d[1]), "+f"(d[2]), "+f"(d[3])
        : "r"(a0), "r"(a1), "r"(a2), "r"(a3), "r"(b0), "r"(b1));
}

// ---------------- preprocessing -----------------------------------------
__global__ void build_hist_kernel(const void* ei) {
    __shared__ int s_is64;
    if (threadIdx.x == 0) {
        const unsigned int* u = (const unsigned int*)ei;
        int is64 = 1;
        for (int k = 0; k < 8; k++)
            if (u[2 * k + 1] != 0u) is64 = 0;
        s_is64 = is64;
    }
    if (blockIdx.x == 0 && threadIdx.x < NB_SCAN)
        g_state[threadIdx.x] = 0u;
    __syncthreads();

    int e = blockIdx.x * blockDim.x + threadIdx.x;
    if (e >= ETOT) return;
    int s, d;
    if (e < EE) {
        if (s_is64) {
            const long long* p = (const long long*)ei;
            s = (int)p[e]; d = (int)p[EE + e];
        } else {
            const int* p = (const int*)ei;
            s = p[e]; d = p[EE + e];
        }
    } else {
        s = d = e - EE;
    }
    g_src[e] = s;
    g_dst[e] = d;
    atomicAdd(&g_deg[d], 1);
}

__global__ __launch_bounds__(1024) void scan_kernel() {
    __shared__ int wsum[32];
    __shared__ int s_excl;
    int tid = threadIdx.x, b = blockIdx.x;
    int lane = tid & 31, wid = tid >> 5;
    int i = b * 1024 + tid;
    int v = (i < NN) ? g_deg[i] : 0;

    int x = v;
#pragma unroll
    for (int o = 1; o < 32; o <<= 1) {
        int t = __shfl_up_sync(0xffffffffu, x, o);
        if (lane >= o) x += t;
    }
    if (lane == 31) wsum[wid] = x;
    __syncthreads();
    if (wid == 0) {
        int y = wsum[lane];
#pragma unroll
        for (int o = 1; o < 32; o <<= 1) {
            int t = __shfl_up_sync(0xffffffffu, y, o);
            if (lane >= o) y += t;
        }
        wsum[lane] = y;
    }
    __syncthreads();
    int incl = x + (wid > 0 ? wsum[wid - 1] : 0);
    int agg  = wsum[31];

    if (tid == 0) {
        unsigned ex = 0;
        if (b == 0) {
            atomicExch(&g_state[0], ((unsigned)agg << 2) | 2u);
        } else {
            atomicExch(&g_state[b], ((unsigned)agg << 2) | 1u);
            int j = b - 1;
            while (1) {
                unsigned st;
                do { st = atomicAdd(&g_state[j], 0u); } while ((st & 3u) == 0u);
                ex += st >> 2;
                if ((st & 3u) == 2u) break;
                j--;
            }
            atomicExch(&g_state[b], ((ex + (unsigned)agg) << 2) | 2u);
        }
        s_excl = (int)ex;
    }
    __syncthreads();
    if (i < NN) {
        int e = s_excl + incl - v;
        g_off[i] = e;
        g_cur[i] = e;
    }
    if (i == 0) g_off[NN] = ETOT;
}

__global__ void scatter_kernel() {
    int e = blockIdx.x * blockDim.x + threadIdx.x;
    if (e >= ETOT) return;
    int slot = atomicAdd(&g_cur[g_dst[e]], 1);
    g_csr[slot] = g_src[e];
}

// ---------------- W1 prepack: fp32 [K,N] -> fp16 [N,K] -------------------
__global__ void packw1_kernel(const float* __restrict__ W1) {
    int i = blockIdx.x * blockDim.x + threadIdx.x;
    if (i >= FIN * HC) return;
    int n = i >> 8, k = i & 255;                  // i = n*256 + k
    g_w1t[i] = __float2half(W1[k * HC + n]);
}

// ---------------- GEMM1 via mma.sync (HMMA) -------------------------------
// h1 = x[NN,256] @ W1[256,128]; CTA 128x128, 8 warps 4x2, warp tile 32x64.
// K in 4 chunks of 64; A fp32->fp16 inline; B from W1^T fp16 prepack.
__global__ __launch_bounds__(256) void gemm1h_kernel(const float* __restrict__ x) {
    __shared__ __half As [128][72];   // [m][k] padded (+8 halves)
    __shared__ __half Bsn[128][72];   // [n][k] padded
    int tid = threadIdx.x;
    int warp = tid >> 5, lane = tid & 31;
    int warp_m = warp & 3, warp_n = warp >> 2;   // 4 x 2
    int g = lane >> 2, tg = lane & 3;
    int row0 = blockIdx.x * 128;

    int arow = tid >> 1, ako = (tid & 1) * 32;   // A fill mapping
    int gr_a = row0 + arow;

    float acc[2][8][4];
#pragma unroll
    for (int mt = 0; mt < 2; mt++)
#pragma unroll
        for (int j = 0; j < 8; j++)
#pragma unroll
            for (int q = 0; q < 4; q++) acc[mt][j][q] = 0.f;

    float4 pa[8];
    uint4  pb[4];
    // prefetch chunk 0
#pragma unroll
    for (int i = 0; i < 8; i++) {
        pa[i] = (gr_a < NN) ? *(const float4*)&x[gr_a * FIN + ako + i * 4]
                            : make_float4(0.f, 0.f, 0.f, 0.f);
    }
#pragma unroll
    for (int i = 0; i < 4; i++)
        pb[i] = *(const uint4*)&g_w1t[arow * FIN + ako + i * 8];

    for (int c = 0; c < 4; c++) {
        // store prefetched chunk to smem
#pragma unroll
        for (int i = 0; i < 8; i++) {
            uint2 hv;
            hv.x = h2u(pa[i].x, pa[i].y);
            hv.y = h2u(pa[i].z, pa[i].w);
            *(uint2*)&As[arow][ako + i * 4] = hv;
        }
#pragma unroll
        for (int i = 0; i < 4; i++)
            *(uint4*)&Bsn[arow][ako + i * 8] = pb[i];
        __syncthreads();

        // prefetch next chunk while computing
        if (c < 3) {
            int kc = (c + 1) * 64;
#pragma unroll
            for (int i = 0; i < 8; i++) {
                pa[i] = (gr_a < NN) ? *(const float4*)&x[gr_a * FIN + kc + ako + i * 4]
                                    : make_float4(0.f, 0.f, 0.f, 0.f);
            }
#pragma unroll
            for (int i = 0; i < 4; i++)
                pb[i] = *(const uint4*)&g_w1t[arow * FIN + kc + ako + i * 8];
        }

        // 4 k16 steps over this 64-wide chunk
#pragma unroll
        for (int ks = 0; ks < 4; ks++) {
            int kb = ks * 16;
            unsigned af[2][4];
#pragma unroll
            for (int mt = 0; mt < 2; mt++) {
                int r = warp_m * 32 + mt * 16 + g;
                af[mt][0] = *(const unsigned*)&As[r][kb + tg * 2];
                af[mt][1] = *(const unsigned*)&As[r + 8][kb + tg * 2];
                af[mt][2] = *(const unsigned*)&As[r][kb + 8 + tg * 2];
                af[mt][3] = *(const unsigned*)&As[r + 8][kb + 8 + tg * 2];
            }
            unsigned bf[8][2];
#pragma unroll
            for (int j = 0; j < 8; j++) {
                int nr = warp_n * 64 + j * 8 + g;
                bf[j][0] = *(const unsigned*)&Bsn[nr][kb + tg * 2];
                bf[j][1] = *(const unsigned*)&Bsn[nr][kb + 8 + tg * 2];
            }
#pragma unroll
            for (int mt = 0; mt < 2; mt++)
#pragma unroll
                for (int j = 0; j < 8; j++)
                    mma16816(acc[mt][j], af[mt][0], af[mt][1], af[mt][2], af[mt][3],
                             bf[j][0], bf[j][1]);
        }
        __syncthreads();
    }

    // epilogue: store h1 as fp16 half2 pairs
    __half* h1h = (__half*)g_h1h;
#pragma unroll
    for (int mt = 0; mt < 2; mt++) {
        int gr0 = row0 + warp_m * 32 + mt * 16 + g;
        int gr1 = gr0 + 8;
#pragma unroll
        for (int j = 0; j < 8; j++) {
            int col = warp_n * 64 + j * 8 + tg * 2;
            if (gr0 < NN)
                *(unsigned*)&h1h[gr0 * HC + col] = h2u(acc[mt][j][0], acc[mt][j][1]);
            if (gr1 < NN)
                *(unsigned*)&h1h[gr1 * HC + col] = h2u(acc[mt][j][2], acc[mt][j][3]);
        }
    }
}

// ---------------- attention logits layer 1 (fp16 read) -------------------
__global__ void att1_kernel(const float* __restrict__ asv,
                            const float* __restrict__ adv) {
    int idx = blockIdx.x * blockDim.x + threadIdx.x;
    if (idx >= NN * 8) return;
    int n = idx >> 3, h = idx & 7;
    const __half* h1h = (const __half*)g_h1h;
    const uint4* p = (const uint4*)&h1h[n * HC + h * 16];
    uint4 v0 = p[0], v1 = p[1];
    unsigned w[8] = {v0.x, v0.y, v0.z, v0.w, v1.x, v1.y, v1.z, v1.w};
    float s = 0.f, d = 0.f;
#pragma unroll
    for (int q = 0; q < 8; q++) {
        float2 f = u_to_f2(w[q]);
        int c = h * 16 + q * 2;
        s += f.x * asv[c] + f.y * asv[c + 1];
        d += f.x * adv[c] + f.y * adv[c + 1];
    }
    g_as1[idx] = s;
    g_ad1[idx] = d;
}

// ---------------- layer 1 aggregation (fp16 gather) ----------------------
__global__ __launch_bounds__(256) void agg1_kernel(const float* __restrict__ b1) {
    int gw = (blockIdx.x * blockDim.x + threadIdx.x) >> 5;
    int lane = threadIdx.x & 31;
    if (gw >= NN) return;
    int n = gw;
    int beg = g_off[n], end = g_off[n + 1];

    int h8 = lane & 7;
    int eg = lane >> 3;
    float adst = g_ad1[n * 8 + h8];

    float mymax = -1e30f;
    for (int i = beg + eg; i < end; i += 4) {
        int s = g_csr[i];
        float ev = g_as1[s * 8 + h8] + adst;
        ev = ev > 0.f ? ev : NSLOPE * ev;
        mymax = fmaxf(mymax, ev);
    }
    mymax = fmaxf(mymax, __shfl_xor_sync(0xffffffffu, mymax, 8));
    mymax = fmaxf(mymax, __shfl_xor_sync(0xffffffffu, mymax, 16));
    float m = mymax;

    float acc0 = 0.f, acc1 = 0.f, acc2 = 0.f, acc3 = 0.f;
    float denom = 0.f;
    int head = lane >> 2;
    const uint2* h1v = (const uint2*)g_h1h;

    int i = beg;
    for (; i + 2 <= end; i += 2) {
        int s0 = g_csr[i], s1 = g_csr[i + 1];
        uint2 r0 = h1v[s0 * 32 + lane];
        uint2 r1 = h1v[s1 * 32 + lane];
        float p0 = 0.f, p1 = 0.f;
        if (lane < 8) {
            float e0 = g_as1[s0 * 8 + lane] + adst;
            e0 = e0 > 0.f ? e0 : NSLOPE * e0;
            p0 = __expf(e0 - m);
            float e1 = g_as1[s1 * 8 + lane] + adst;
            e1 = e1 > 0.f ? e1 : NSLOPE * e1;
            p1 = __expf(e1 - m);
            denom += p0 + p1;
        }
        float ph0 = __shfl_sync(0xffffffffu, p0, head);
        float ph1 = __shfl_sync(0xffffffffu, p1, head);
        float2 f00 = u_to_f2(r0.x);
        float2 f01 = u_to_f2(r0.y);
        float2 f10 = u_to_f2(r1.x);
        float2 f11 = u_to_f2(r1.y);
        acc0 += ph0 * f00.x + ph1 * f10.x;
        acc1 += ph0 * f00.y + ph1 * f10.y;
        acc2 += ph0 * f01.x + ph1 * f11.x;
        acc3 += ph0 * f01.y + ph1 * f11.y;
    }
    for (; i < end; i++) {
        int s = g_csr[i];
        uint2 r0 = h1v[s * 32 + lane];
        float p = 0.f;
        if (lane < 8) {
            float ev = g_as1[s * 8 + lane] + adst;
            ev = ev > 0.f ? ev : NSLOPE * ev;
            p = __expf(ev - m);
            denom += p;
        }
        float ph = __shfl_sync(0xffffffffu, p, head);
        float2 f0 = u_to_f2(r0.x);
        float2 f1 = u_to_f2(r0.y);
        acc0 += ph * f0.x; acc1 += ph * f0.y;
        acc2 += ph * f1.x; acc3 += ph * f1.y;
    }
    float dh = __shfl_sync(0xffffffffu, denom, head);
    float inv = 1.f / (dh + 1e-16f);
    int ch = lane * 4;
    float v[4] = {acc0 * inv + b1[ch], acc1 * inv + b1[ch + 1],
                  acc2 * inv + b1[ch + 2], acc3 * inv + b1[ch + 3]};
#pragma unroll
    for (int j = 0; j < 4; j++)
        v[j] = v[j] > 0.f ? v[j] : expm1f(v[j]);
    ((float4*)g_out1)[n * 32 + lane] = make_float4(v[0], v[1], v[2], v[3]);
}

// ---------------- GEMM2 + fused att2 -------------------------------------
__global__ __launch_bounds__(320) void gemm2_kernel(const float* __restrict__ W,
                                                    const float* __restrict__ asv,
                                                    const float* __restrict__ adv) {
    __shared__ float s_w[HC * NC];       // 20 KB
    __shared__ float s_x[64 * HC];       // 32 KB
    int c = threadIdx.x;   // 0..39
    int r = threadIdx.y;   // 0..7
    int t = threadIdx.y * 40 + threadIdx.x;
    int row0 = blockIdx.x * 64;

    for (int i = t; i < HC * NC; i += 320) s_w[i] = W[i];
    for (int i = t; i < 64 * (HC / 4); i += 320) {
        int rr = i >> 5, kq = (i & 31) * 4;
        int gr = row0 + rr;
        float4 v = make_float4(0.f, 0.f, 0.f, 0.f);
        if (gr < NN) v = *(const float4*)&g_out1[gr * HC + kq];
        *(float4*)&s_x[rr * HC + kq] = v;
    }
    __syncthreads();

    float acc[8] = {0.f, 0.f, 0.f, 0.f, 0.f, 0.f, 0.f, 0.f};
    for (int k4 = 0; k4 < HC; k4 += 4) {
        float w0 = s_w[(k4 + 0) * NC + c];
        float w1 = s_w[(k4 + 1) * NC + c];
        float w2 = s_w[(k4 + 2) * NC + c];
        float w3 = s_w[(k4 + 3) * NC + c];
#pragma unroll
        for (int i = 0; i < 8; i++) {
            float4 xv = *(const float4*)&s_x[(r + 8 * i) * HC + k4];
            acc[i] += w0 * xv.x + w1 * xv.y + w2 * xv.z + w3 * xv.w;
        }
    }
#pragma unroll
    for (int i = 0; i < 8; i++) {
        int gr = row0 + r + 8 * i;
        if (gr < NN) g_h2[gr * NC + c] = acc[i];
    }

    __syncthreads();
    float* s_h2 = s_x;
#pragma unroll
    for (int i = 0; i < 8; i++)
        s_h2[(r + 8 * i) * NC + c] = acc[i];
    __syncthreads();
    if (t < 64) {
        int gr = row0 + t;
        if (gr < NN) {
            float s = 0.f, d = 0.f;
#pragma unroll
            for (int cc = 0; cc < NC; cc++) {
                float hv = s_h2[t * NC + cc];
                s += hv * asv[cc];
                d += hv * adv[cc];
            }
            g_as2[gr] = s;
            g_ad2[gr] = d;
        }
    }
}

// ---------------- layer 2 aggregation + log_softmax ----------------------
__global__ __launch_bounds__(256) void agg2_kernel(const float* __restrict__ b2,
                                                   float* __restrict__ out,
                                                   int write_both) {
    int gw = (blockIdx.x * blockDim.x + threadIdx.x) >> 5;
    int lane = threadIdx.x & 31;
    if (gw >= NN) return;
    int n = gw;
    int beg = g_off[n], end = g_off[n + 1];
    float adst = g_ad2[n];

    float mymax = -1e30f;
    for (int i = beg + lane; i < end; i += 32) {
        int s = g_csr[i];
        float ev = g_as2[s] + adst;
        ev = ev > 0.f ? ev : NSLOPE * ev;
        mymax = fmaxf(mymax, ev);
    }
#pragma unroll
    for (int o = 16; o > 0; o >>= 1)
        mymax = fmaxf(mymax, __shfl_xor_sync(0xffffffffu, mymax, o));
    float m = mymax;

    float acc0 = 0.f, acc1 = 0.f, denom = 0.f;
    int i = beg;
    for (; i + 2 <= end; i += 2) {
        int s0 = g_csr[i], s1 = g_csr[i + 1];
        float x00 = g_h2[s0 * NC + lane];
        float x10 = g_h2[s1 * NC + lane];
        float x01 = (lane < 8) ? g_h2[s0 * NC + 32 + lane] : 0.f;
        float x11 = (lane < 8) ? g_h2[s1 * NC + 32 + lane] : 0.f;
        float e0 = g_as2[s0] + adst; e0 = e0 > 0.f ? e0 : NSLOPE * e0;
        float e1 = g_as2[s1] + adst; e1 = e1 > 0.f ? e1 : NSLOPE * e1;
        float p0 = __expf(e0 - m), p1 = __expf(e1 - m);
        denom += p0 + p1;
        acc0 += p0 * x00 + p1 * x10;
        acc1 += p0 * x01 + p1 * x11;
    }
    for (; i < end; i++) {
        int s = g_csr[i];
        float x0 = g_h2[s * NC + lane];
        float x1 = (lane < 8) ? g_h2[s * NC + 32 + lane] : 0.f;
        float ev = g_as2[s] + adst;
        ev = ev > 0.f ? ev : NSLOPE * ev;
        float p = __expf(ev - m);
        denom += p;
        acc0 += p * x0;
        acc1 += p * x1;
    }
    float inv = 1.f / (denom + 1e-16f);
    float v0 = acc0 * inv + b2[lane];
    float v1 = (lane < 8) ? acc1 * inv + b2[32 + lane] : -1e30f;

    float rmax = fmaxf(v0, v1);
#pragma unroll
    for (int o = 16; o > 0; o >>= 1)
        rmax = fmaxf(rmax, __shfl_xor_sync(0xffffffffu, rmax, o));
    float se = expf(v0 - rmax) + ((lane < 8) ? expf(v1 - rmax) : 0.f);
#pragma unroll
    for (int o = 16; o > 0; o >>= 1)
        se += __shfl_xor_sync(0xffffffffu, se, o);
    float lse = rmax + logf(se);

    out[n * NC + lane] = v0;
    if (lane < 8) out[n * NC + 32 + lane] = v1;
    if (write_both) {
        float* o2 = out + (size_t)NN * NC;
        o2[n * NC + lane] = v0 - lse;
        if (lane < 8) o2[n * NC + 32 + lane] = v1 - lse;
    }
}

// ---------------- launch --------------------------------------------------
extern "C" void kernel_launch(void* const* d_in, const int* in_sizes, int n_in,
                              void* d_out, int out_size) {
    const float* x   = (const float*)d_in[0];
    const void*  ei  = d_in[1];
    const float* W1  = (const float*)d_in[3];
    const float* as1 = (const float*)d_in[4];
    const float* ad1 = (const float*)d_in[5];
    const float* b1  = (const float*)d_in[6];
    const float* W2  = (const float*)d_in[7];
    const float* as2 = (const float*)d_in[8];
    const float* ad2 = (const float*)d_in[9];
    const float* b2  = (const float*)d_in[10];
    float* out = (float*)d_out;
    (void)in_sizes; (void)n_in;

    void* deg_ptr = nullptr;
    cudaGetSymbolAddress(&deg_ptr, g_deg);
    cudaMemsetAsync(deg_ptr, 0, NN * sizeof(int));

    packw1_kernel<<<(FIN * HC + 255) / 256, 256>>>(W1);
    build_hist_kernel<<<(ETOT + 255) / 256, 256>>>(ei);
    scan_kernel<<<NB_SCAN, 1024>>>();
    scatter_kernel<<<(ETOT + 255) / 256, 256>>>();

    gemm1h_kernel<<<(NN + 127) / 128, 256>>>(x);
    att1_kernel<<<(NN * 8 + 255) / 256, 256>>>(as1, ad1);
    agg1_kernel<<<(NN * 32 + 255) / 256, 256>>>(b1);

    gemm2_kernel<<<(NN + 63) / 64, dim3(40, 8)>>>(W2, as2, ad2);

    int write_both = (out_size >= 2 * NN * NC) ? 1 : 0;
    agg2_kernel<<<(NN * 32 + 255) / 256, 256>>>(b2, out, write_both);
}